// round 7
// baseline (speedup 1.0000x reference)
#include <cuda_runtime.h>
#include <cstdint>
#include <math.h>

#define NBATCH 16
#define NNODE  1024
#define HD     256
#define NROWS  (NBATCH*NNODE)
#define TOTEL  16777216
#define HALFN  8388608u

__device__ float d_hid[NROWS*768];
__device__ float d_hs [NROWS*HD];
__device__ float d_g  [NROWS*HD];
__device__ float d_u1 [NROWS*HD];
__device__ float d_u2 [NROWS*HD];
__device__ float d_u3 [NROWS*HD];
__device__ float d_u4 [NROWS*HD];
__device__ float d_hp [NROWS*HD];
__device__ float d_mid[NROWS*HD];
__device__ float d_logits[TOTEL];
__device__ float d_dis[NROWS];
__device__ float d_invdeg[NROWS];
__device__ float d_Rv[NROWS];
__device__ float d_Cv[NROWS];
__device__ float d_Tv[NROWS];

__device__ __forceinline__ float leakyf(float x){ return x > 0.f ? x : 0.01f*x; }

__global__ void k_adj_stats(const float* __restrict__ adj){
    int row  = blockIdx.x*8 + (threadIdx.x>>5);
    int lane = threadIdx.x & 31;
    const float* a = adj + (size_t)row*NNODE;
    float s = 0.f;
    #pragma unroll
    for (int k=0;k<32;k++) s += a[lane + 32*k];
    #pragma unroll
    for (int o=16;o;o>>=1) s += __shfl_xor_sync(0xffffffffu, s, o);
    if (lane==0){ d_dis[row] = rsqrtf(s + 1.f); d_invdeg[row] = 1.f/s; }
}

__global__ void k_scale_hs(int off){
    int idx = blockIdx.x*256 + threadIdx.x;
    int row = idx >> 8, col = idx & 255;
    d_hs[idx] = d_dis[row] * d_hid[(size_t)row*768 + off + col];
}

#define BM 128
#define BN 128
#define BK 8
// batched adj GEMM: acc = adj[b] @ B; mode1: out=leaky(dis*(acc+aux)); mode2: out=0.5*(aux+acc*invdeg)
__global__ __launch_bounds__(256,2) void k_bgemm(
    const float* __restrict__ Aadj, const float* __restrict__ B, int ldb,
    float* __restrict__ Cc, int ldc, int mode,
    const float* __restrict__ aux, int ldaux, const float* __restrict__ vec)
{
    int bb = blockIdx.z;
    int n0 = blockIdx.x * BN;
    int m0 = blockIdx.y * BM;
    const float* Ab = Aadj + (size_t)bb*NNODE*NNODE;
    __shared__ float As[BK][BM];
    __shared__ float Bs[BK][BN];
    int tid  = threadIdx.x;
    int arow = tid >> 1;
    int akg  = (tid & 1) * 4;
    int bkr  = tid >> 5;
    int bc4  = (tid & 31) * 4;
    int ty = tid >> 4, tx = tid & 15;
    float acc[8][8] = {};
    for (int k0 = 0; k0 < NNODE; k0 += BK){
        float4 av = *(const float4*)(Ab + (size_t)(m0+arow)*NNODE + k0 + akg);
        As[akg+0][arow]=av.x; As[akg+1][arow]=av.y; As[akg+2][arow]=av.z; As[akg+3][arow]=av.w;
        float4 bv = *(const float4*)(B + (size_t)(bb*NNODE + k0 + bkr)*ldb + n0 + bc4);
        *(float4*)&Bs[bkr][bc4] = bv;
        __syncthreads();
        #pragma unroll
        for (int k=0;k<BK;k++){
            float ar[8], br[8];
            #pragma unroll
            for (int m=0;m<8;m++) ar[m] = As[k][ty*8+m];
            #pragma unroll
            for (int n=0;n<8;n++) br[n] = Bs[k][tx*8+n];
            #pragma unroll
            for (int m=0;m<8;m++)
                #pragma unroll
                for (int n=0;n<8;n++)
                    acc[m][n] = fmaf(ar[m], br[n], acc[m][n]);
        }
        __syncthreads();
    }
    #pragma unroll
    for (int m=0;m<8;m++){
        size_t gi = (size_t)(bb*NNODE + m0 + ty*8 + m);
        float dv = vec[gi];
        #pragma unroll
        for (int n=0;n<8;n++){
            int col = n0 + tx*8 + n;
            float v;
            if (mode == 1) v = leakyf(dv * (acc[m][n] + aux[gi*(size_t)ldaux + col]));
            else           v = 0.5f * (aux[gi*(size_t)ldaux + col] + acc[m][n]*dv);
            Cc[gi*(size_t)ldc + col] = v;
        }
    }
}

// dense NT GEMM: C = act(A @ W^T + bias); act 0:none 1:leaky 2:tanh*40
__global__ __launch_bounds__(256,2) void k_gemm_nt(
    const float* __restrict__ A, int lda,
    const float* __restrict__ W, int K, const float* __restrict__ bias,
    float* __restrict__ Cc, int ldc, int act)
{
    int n0 = blockIdx.x * BN;
    int m0 = blockIdx.y * BM;
    __shared__ float As[BK][BM];
    __shared__ float Bs[BK][BN];
    int tid  = threadIdx.x;
    int arow = tid >> 1;
    int akg  = (tid & 1) * 4;
    int ty = tid >> 4, tx = tid & 15;
    float acc[8][8] = {};
    for (int k0 = 0; k0 < K; k0 += BK){
        float4 av = *(const float4*)(A + (size_t)(m0+arow)*lda + k0 + akg);
        As[akg+0][arow]=av.x; As[akg+1][arow]=av.y; As[akg+2][arow]=av.z; As[akg+3][arow]=av.w;
        float4 wv = *(const float4*)(W + (size_t)(n0+arow)*K + k0 + akg);
        Bs[akg+0][arow]=wv.x; Bs[akg+1][arow]=wv.y; Bs[akg+2][arow]=wv.z; Bs[akg+3][arow]=wv.w;
        __syncthreads();
        #pragma unroll
        for (int k=0;k<BK;k++){
            float ar[8], br[8];
            #pragma unroll
            for (int m=0;m<8;m++) ar[m] = As[k][ty*8+m];
            #pragma unroll
            for (int n=0;n<8;n++) br[n] = Bs[k][tx*8+n];
            #pragma unroll
            for (int m=0;m<8;m++)
                #pragma unroll
                for (int n=0;n<8;n++)
                    acc[m][n] = fmaf(ar[m], br[n], acc[m][n]);
        }
        __syncthreads();
    }
    #pragma unroll
    for (int m=0;m<8;m++){
        size_t gi = (size_t)(m0 + ty*8 + m);
        #pragma unroll
        for (int n=0;n<8;n++){
            int col = n0 + tx*8 + n;
            float v = acc[m][n] + bias[col];
            if (act == 1) v = leakyf(v);
            else if (act == 2) v = tanhf(v) * 40.0f;
            Cc[gi*(size_t)ldc + col] = v;
        }
    }
}

// channel attention + weighted mean over 4 channels
__global__ void k_attn(int off, const float* __restrict__ avec){
    int i = blockIdx.x, d = threadIdx.x;
    size_t b = (size_t)i*HD + d;
    float x  = d_hid[(size_t)i*768 + off + d];
    float c0 = d_g[b];
    float u1 = d_u1[b], u2 = d_u2[b], u4 = d_u4[b];
    float c1 = fabsf(x - u1), c2 = fabsf(u1 - u2), c3 = fabsf(u2 - u4);
    float ah = avec[256 + d];
    float e0 = fmaxf(c0, 0.f)*ah, e1 = c1*ah, e2 = c2*ah, e3 = c3*ah;
    #pragma unroll
    for (int o=16;o;o>>=1){
        e0 += __shfl_xor_sync(0xffffffffu, e0, o);
        e1 += __shfl_xor_sync(0xffffffffu, e1, o);
        e2 += __shfl_xor_sync(0xffffffffu, e2, o);
        e3 += __shfl_xor_sync(0xffffffffu, e3, o);
    }
    __shared__ float sred[4][8];
    __shared__ float tot[4];
    int w = d >> 5;
    if ((d & 31) == 0){ sred[0][w]=e0; sred[1][w]=e1; sred[2][w]=e2; sred[3][w]=e3; }
    __syncthreads();
    if (d < 4){
        float t = 0.f;
        #pragma unroll
        for (int ww=0; ww<8; ww++) t += sred[d][ww];
        tot[d] = t;
    }
    __syncthreads();
    float E0=tot[0], E1=tot[1], E2=tot[2], E3=tot[3];
    float m = fmaxf(fmaxf(E0,E1), fmaxf(E2,E3));
    float w0=__expf(E0-m), w1=__expf(E1-m), w2=__expf(E2-m), w3=__expf(E3-m);
    float inv = 0.25f / (w0+w1+w2+w3);
    d_hp[b] = inv * (w0*c0 + w1*c1 + w2*c2 + w3*c3);
}

// Threefry-2x32-20, key (0,42)
__device__ __forceinline__ void threefry(unsigned x0, unsigned x1, unsigned& o0, unsigned& o1){
    const unsigned ks0 = 0u, ks1 = 42u, ks2 = 0x1BD11BDAu ^ 42u;
    x0 += ks0; x1 += ks1;
#define TFR(r) { x0 += x1; x1 = (x1<<(r))|(x1>>(32-(r))); x1 ^= x0; }
    TFR(13) TFR(15) TFR(26) TFR(6)   x0+=ks1; x1+=ks2+1u;
    TFR(17) TFR(29) TFR(16) TFR(24)  x0+=ks2; x1+=ks0+2u;
    TFR(13) TFR(15) TFR(26) TFR(6)   x0+=ks0; x1+=ks1+3u;
    TFR(17) TFR(29) TFR(16) TFR(24)  x0+=ks1; x1+=ks2+4u;
    TFR(13) TFR(15) TFR(26) TFR(6)   x0+=ks2; x1+=ks0+5u;
#undef TFR
    o0 = x0; o1 = x1;
}

__device__ __forceinline__ float gumb(unsigned bits){
    float u = __uint_as_float((bits >> 9) | 0x3F800000u) - 1.0f;
    return -logf(-logf(u + 1e-20f) + 1e-20f) * 0.05f;
}

// JAX partitionable threefry: per element t, counter = uint64 t -> (hi=0, lo=t),
// 32-bit output = o0 ^ o1
__global__ void k_z0(float* __restrict__ z0){
    unsigned t = blockIdx.x*256u + threadIdx.x;
    unsigned o0, o1;
    threefry(0u, t, o0, o1);
    z0[t] = (d_logits[t] + gumb(o0 ^ o1)) * 10.0f;
}

__global__ void k_zeroC(){ d_Cv[blockIdx.x*256 + threadIdx.x] = 0.f; }

// R[row] = lse_j(Z[row,:] - C[b,:]); one warp per row
__global__ void k_row_lse(const float* __restrict__ Z){
    int row  = blockIdx.x*8 + (threadIdx.x>>5);
    int lane = threadIdx.x & 31;
    int b    = row >> 10;
    const float* z = Z + (size_t)row*NNODE;
    const float* c = d_Cv + b*NNODE;
    float v[32];
    float m = -3.4e38f;
    #pragma unroll
    for (int k=0;k<32;k++){ v[k] = z[lane + 32*k] - c[lane + 32*k]; m = fmaxf(m, v[k]); }
    #pragma unroll
    for (int o=16;o;o>>=1) m = fmaxf(m, __shfl_xor_sync(0xffffffffu, m, o));
    float s = 0.f;
    #pragma unroll
    for (int k=0;k<32;k++) s += __expf(v[k] - m);
    #pragma unroll
    for (int o=16;o;o>>=1) s += __shfl_xor_sync(0xffffffffu, s, o);
    if (lane==0) d_Rv[row] = m + __logf(s);
}

// C[b,j] = lse_i(Z[b,i,j] - R[b,i]); block = (b, 64-col chunk), 4 row-quarters
__global__ void k_col_lse(const float* __restrict__ Z){
    int b     = blockIdx.x >> 4;
    int chunk = blockIdx.x & 15;
    int jc    = threadIdx.x & 63;
    int q     = threadIdx.x >> 6;
    __shared__ float rs[NNODE];
    for (int k=threadIdx.x; k<NNODE; k+=256) rs[k] = d_Rv[b*NNODE + k];
    __syncthreads();
    const float* z = Z + (size_t)b*NNODE*NNODE + chunk*64 + jc;
    int i0 = q*256;
    float m0=-3.4e38f, m1=-3.4e38f, m2=-3.4e38f, m3=-3.4e38f;
    for (int i=i0; i<i0+256; i+=4){
        m0 = fmaxf(m0, z[(size_t)(i+0)*NNODE] - rs[i+0]);
        m1 = fmaxf(m1, z[(size_t)(i+1)*NNODE] - rs[i+1]);
        m2 = fmaxf(m2, z[(size_t)(i+2)*NNODE] - rs[i+2]);
        m3 = fmaxf(m3, z[(size_t)(i+3)*NNODE] - rs[i+3]);
    }
    float m = fmaxf(fmaxf(m0,m1), fmaxf(m2,m3));
    float s0=0.f,s1=0.f,s2=0.f,s3=0.f;
    for (int i=i0; i<i0+256; i+=4){
        s0 += __expf(z[(size_t)(i+0)*NNODE] - rs[i+0] - m);
        s1 += __expf(z[(size_t)(i+1)*NNODE] - rs[i+1] - m);
        s2 += __expf(z[(size_t)(i+2)*NNODE] - rs[i+2] - m);
        s3 += __expf(z[(size_t)(i+3)*NNODE] - rs[i+3] - m);
    }
    __shared__ float sm[4][64], ss[4][64];
    sm[q][jc] = m; ss[q][jc] = s0+s1+s2+s3;
    __syncthreads();
    if (threadIdx.x < 64){
        int j = threadIdx.x;
        float M = fmaxf(fmaxf(sm[0][j],sm[1][j]), fmaxf(sm[2][j],sm[3][j]));
        float S = ss[0][j]*__expf(sm[0][j]-M) + ss[1][j]*__expf(sm[1][j]-M)
                + ss[2][j]*__expf(sm[2][j]-M) + ss[3][j]*__expf(sm[3][j]-M);
        d_Cv[b*NNODE + chunk*64 + j] = M + __logf(S);
    }
}

// T[b,j] = sum_i exp(Z - R - C) (row-normalized => args <= 0)
__global__ void k_col_T(const float* __restrict__ Z){
    int b     = blockIdx.x >> 4;
    int chunk = blockIdx.x & 15;
    int jc    = threadIdx.x & 63;
    int q     = threadIdx.x >> 6;
    __shared__ float rs[NNODE];
    for (int k=threadIdx.x; k<NNODE; k+=256) rs[k] = d_Rv[b*NNODE + k];
    __syncthreads();
    float cj = d_Cv[b*NNODE + chunk*64 + jc];
    const float* z = Z + (size_t)b*NNODE*NNODE + chunk*64 + jc;
    int i0 = q*256;
    float s0=0.f,s1=0.f,s2=0.f,s3=0.f;
    for (int i=i0; i<i0+256; i+=4){
        s0 += __expf(z[(size_t)(i+0)*NNODE] - rs[i+0] - cj);
        s1 += __expf(z[(size_t)(i+1)*NNODE] - rs[i+1] - cj);
        s2 += __expf(z[(size_t)(i+2)*NNODE] - rs[i+2] - cj);
        s3 += __expf(z[(size_t)(i+3)*NNODE] - rs[i+3] - cj);
    }
    __shared__ float ss[4][64];
    ss[q][jc] = s0+s1+s2+s3;
    __syncthreads();
    if (threadIdx.x < 64){
        int j = threadIdx.x;
        d_Tv[b*NNODE + chunk*64 + j] = ss[0][j]+ss[1][j]+ss[2][j]+ss[3][j];
    }
}

__global__ void k_final(const float* __restrict__ Z, float* __restrict__ P){
    size_t t = (size_t)blockIdx.x*256 + threadIdx.x;
    int row = (int)(t >> 10);
    int b   = row >> 10;
    int j   = (int)(t & 1023);
    P[t] = __expf(Z[t] - d_Rv[row] - d_Cv[b*NNODE + j]) / d_Tv[b*NNODE + j];
}

extern "C" void kernel_launch(void* const* d_in, const int* in_sizes, int n_in,
                              void* d_out, int out_size) {
    const float* X      = (const float*)d_in[0];
    const float* adj    = (const float*)d_in[1];
    const float* w_in   = (const float*)d_in[2];
    const float* b_in   = (const float*)d_in[3];
    const float* cw1    = (const float*)d_in[4];
    const float* cb1    = (const float*)d_in[5];
    const float* cw2    = (const float*)d_in[6];
    const float* cb2    = (const float*)d_in[7];
    const float* ca     = (const float*)d_in[8];
    const float* m1w    = (const float*)d_in[9];
    const float* m1b    = (const float*)d_in[10];
    const float* m2w    = (const float*)d_in[11];
    const float* m2b    = (const float*)d_in[12];
    float* Pout = (float*)d_out;
    float* Z0   = Pout + (size_t)TOTEL;

    float *hid, *hs, *g, *u1, *u2, *u3, *u4, *hp, *mid, *lg;
    cudaGetSymbolAddress((void**)&hid, d_hid);
    cudaGetSymbolAddress((void**)&hs,  d_hs);
    cudaGetSymbolAddress((void**)&g,   d_g);
    cudaGetSymbolAddress((void**)&u1,  d_u1);
    cudaGetSymbolAddress((void**)&u2,  d_u2);
    cudaGetSymbolAddress((void**)&u3,  d_u3);
    cudaGetSymbolAddress((void**)&u4,  d_u4);
    cudaGetSymbolAddress((void**)&hp,  d_hp);
    cudaGetSymbolAddress((void**)&mid, d_mid);
    cudaGetSymbolAddress((void**)&lg,  d_logits);
    float *dis, *invdeg;
    cudaGetSymbolAddress((void**)&dis,    d_dis);
    cudaGetSymbolAddress((void**)&invdeg, d_invdeg);

    k_adj_stats<<<NROWS/8, 256>>>(adj);

    // h0 = X @ w_in^T + b_in  (no activation), into d_hid cols [0,256)
    k_gemm_nt<<<dim3(2,128), 256>>>(X, 128, w_in, 128, b_in, hid, 768, 0);

    dim3 bg(2, 8, 16);
    for (int l = 0; l < 2; l++){
        int off  = 256*l;
        int offn = 256*(l+1);
        k_scale_hs<<<NROWS*HD/256, 256>>>(off);
        k_bgemm<<<bg, 256>>>(adj, hs, 256, g,  256, 1, hs, 256, dis);
        k_bgemm<<<bg, 256>>>(adj, hid+off, 768, u1, 256, 2, hid+off, 768, invdeg);
        k_bgemm<<<bg, 256>>>(adj, u1, 256, u2, 256, 2, u1, 256, invdeg);
        k_bgemm<<<bg, 256>>>(adj, u2, 256, u3, 256, 2, u2, 256, invdeg);
        k_bgemm<<<bg, 256>>>(adj, u3, 256, u4, 256, 2, u3, 256, invdeg);
        k_attn<<<NROWS, 256>>>(off, ca + l*512);
        k_gemm_nt<<<dim3(2,128), 256>>>(hp,  256, cw1 + l*65536, 256, cb1 + l*256, mid, 256, 1);
        k_gemm_nt<<<dim3(2,128), 256>>>(mid, 256, cw2 + l*65536, 256, cb2 + l*256, hid + offn, 768, 1);
    }

    // mlp1: leaky(hid[16384,768] @ m1w^T + b) -> mid
    k_gemm_nt<<<dim3(2,128), 256>>>(hid, 768, m1w, 768, m1b, mid, 256, 1);
    // mlp2: tanh(mid @ m2w^T + b)*40 -> logits
    k_gemm_nt<<<dim3(8,128), 256>>>(mid, 256, m2w, 256, m2b, lg, 1024, 2);

    // Z0 = (logits + gumbel)/tau  -> written straight into output (gsinit)
    k_z0<<<TOTEL/256, 256>>>(Z0);

    // Sinkhorn: rank-1 log-domain state (R, C)
    k_zeroC<<<NROWS/256, 256>>>();
    for (int it = 0; it < 20; it++){
        k_row_lse<<<NROWS/8, 256>>>(Z0);
        k_col_lse<<<256, 256>>>(Z0);
    }
    k_row_lse<<<NROWS/8, 256>>>(Z0);   // row normalization of P
    k_col_T  <<<256, 256>>>(Z0);       // col sums
    k_final  <<<TOTEL/256, 256>>>(Z0, Pout);
}

// round 8
// speedup vs baseline: 1.1285x; 1.1285x over previous
#include <cuda_runtime.h>
#include <cstdint>
#include <math.h>

#define NBATCH 16
#define NNODE  1024
#define HD     256
#define NROWS  (NBATCH*NNODE)
#define TOTEL  16777216

__device__ float d_hid[NROWS*768];
__device__ float d_hs [NROWS*HD];
__device__ float d_g  [NROWS*HD];
__device__ float d_u1 [NROWS*HD];
__device__ float d_u2 [NROWS*HD];
__device__ float d_u3 [NROWS*HD];
__device__ float d_u4 [NROWS*HD];
__device__ float d_hp [NROWS*HD];
__device__ float d_mid[NROWS*HD];
__device__ float d_logits[TOTEL];
__device__ float d_dis[NROWS];
__device__ float d_invdeg[NROWS];
__device__ float d_Rv[NROWS];
__device__ float d_Cv[NROWS];
__device__ float d_Tv[NROWS];

__device__ __forceinline__ float leakyf(float x){ return x > 0.f ? x : 0.01f*x; }

__global__ void k_adj_stats(const float* __restrict__ adj){
    int row  = blockIdx.x*8 + (threadIdx.x>>5);
    int lane = threadIdx.x & 31;
    const float* a = adj + (size_t)row*NNODE;
    float s = 0.f;
    #pragma unroll
    for (int k=0;k<32;k++) s += a[lane + 32*k];
    #pragma unroll
    for (int o=16;o;o>>=1) s += __shfl_xor_sync(0xffffffffu, s, o);
    if (lane==0){ d_dis[row] = rsqrtf(s + 1.f); d_invdeg[row] = 1.f/s; }
}

__global__ void k_scale_hs(int off){
    int idx = blockIdx.x*256 + threadIdx.x;
    int row = idx >> 8, col = idx & 255;
    d_hs[idx] = d_dis[row] * d_hid[(size_t)row*768 + off + col];
}

#define BM 128
#define BN 128
#define BK 16

// batched adj GEMM, double-buffered: acc = adj[b] @ B
// mode1: out=leaky(dis*(acc+aux)); mode2: out=0.5*(aux+acc*invdeg)
__global__ __launch_bounds__(256,2) void k_bgemm(
    const float* __restrict__ Aadj, const float* __restrict__ B, int ldb,
    float* __restrict__ Cc, int ldc, int mode,
    const float* __restrict__ aux, int ldaux, const float* __restrict__ vec)
{
    int bb = blockIdx.z;
    int n0 = blockIdx.x * BN;
    int m0 = blockIdx.y * BM;
    const float* Ab = Aadj + (size_t)bb*NNODE*NNODE;
    __shared__ float As[2][BK][BM];
    __shared__ float Bs[2][BK][BN];
    int tid  = threadIdx.x;
    int arow = tid >> 1;
    int acol = (tid & 1) * 8;
    int brow = tid >> 4;
    int bcol = (tid & 15) * 8;
    int ty = tid >> 4, tx = tid & 15;

    const float* aptr = Ab + (size_t)(m0+arow)*NNODE + acol;
    const float* bptr = B + (size_t)(bb*NNODE + brow)*ldb + n0 + bcol;

    float4 a0 = *(const float4*)(aptr);
    float4 a1 = *(const float4*)(aptr + 4);
    float4 b0 = *(const float4*)(bptr);
    float4 b1 = *(const float4*)(bptr + 4);
    As[0][acol+0][arow]=a0.x; As[0][acol+1][arow]=a0.y; As[0][acol+2][arow]=a0.z; As[0][acol+3][arow]=a0.w;
    As[0][acol+4][arow]=a1.x; As[0][acol+5][arow]=a1.y; As[0][acol+6][arow]=a1.z; As[0][acol+7][arow]=a1.w;
    *(float4*)&Bs[0][brow][bcol]   = b0;
    *(float4*)&Bs[0][brow][bcol+4] = b1;
    __syncthreads();

    float acc[8][8] = {};
    const int ntile = NNODE/BK;
    for (int t = 0; t < ntile; t++){
        int cur = t & 1;
        if (t+1 < ntile){
            a0 = *(const float4*)(aptr + (t+1)*BK);
            a1 = *(const float4*)(aptr + (t+1)*BK + 4);
            b0 = *(const float4*)(bptr + (size_t)(t+1)*BK*ldb);
            b1 = *(const float4*)(bptr + (size_t)(t+1)*BK*ldb + 4);
        }
        #pragma unroll
        for (int k=0;k<BK;k++){
            float ar[8], br[8];
            #pragma unroll
            for (int m=0;m<8;m++) ar[m] = As[cur][k][ty*8+m];
            #pragma unroll
            for (int n=0;n<8;n++) br[n] = Bs[cur][k][tx*8+n];
            #pragma unroll
            for (int m=0;m<8;m++)
                #pragma unroll
                for (int n=0;n<8;n++)
                    acc[m][n] = fmaf(ar[m], br[n], acc[m][n]);
        }
        if (t+1 < ntile){
            int nxt = cur ^ 1;
            As[nxt][acol+0][arow]=a0.x; As[nxt][acol+1][arow]=a0.y; As[nxt][acol+2][arow]=a0.z; As[nxt][acol+3][arow]=a0.w;
            As[nxt][acol+4][arow]=a1.x; As[nxt][acol+5][arow]=a1.y; As[nxt][acol+6][arow]=a1.z; As[nxt][acol+7][arow]=a1.w;
            *(float4*)&Bs[nxt][brow][bcol]   = b0;
            *(float4*)&Bs[nxt][brow][bcol+4] = b1;
            __syncthreads();
        }
    }
    #pragma unroll
    for (int m=0;m<8;m++){
        size_t gi = (size_t)(bb*NNODE + m0 + ty*8 + m);
        float dv = vec[gi];
        #pragma unroll
        for (int n=0;n<8;n++){
            int col = n0 + tx*8 + n;
            float v;
            if (mode == 1) v = leakyf(dv * (acc[m][n] + aux[gi*(size_t)ldaux + col]));
            else           v = 0.5f * (aux[gi*(size_t)ldaux + col] + acc[m][n]*dv);
            Cc[gi*(size_t)ldc + col] = v;
        }
    }
}

// dense NT GEMM, double-buffered: C = act(A @ W^T + bias); act 0:none 1:leaky 2:tanh*40
__global__ __launch_bounds__(256,2) void k_gemm_nt(
    const float* __restrict__ A, int lda,
    const float* __restrict__ W, int K, const float* __restrict__ bias,
    float* __restrict__ Cc, int ldc, int act)
{
    int n0 = blockIdx.x * BN;
    int m0 = blockIdx.y * BM;
    __shared__ float As[2][BK][BM];
    __shared__ float Bs[2][BK][BN];
    int tid  = threadIdx.x;
    int arow = tid >> 1;
    int acol = (tid & 1) * 8;
    int ty = tid >> 4, tx = tid & 15;

    const float* aptr = A + (size_t)(m0+arow)*lda + acol;
    const float* wptr = W + (size_t)(n0+arow)*K   + acol;

    float4 a0 = *(const float4*)(aptr);
    float4 a1 = *(const float4*)(aptr + 4);
    float4 w0 = *(const float4*)(wptr);
    float4 w1 = *(const float4*)(wptr + 4);
    As[0][acol+0][arow]=a0.x; As[0][acol+1][arow]=a0.y; As[0][acol+2][arow]=a0.z; As[0][acol+3][arow]=a0.w;
    As[0][acol+4][arow]=a1.x; As[0][acol+5][arow]=a1.y; As[0][acol+6][arow]=a1.z; As[0][acol+7][arow]=a1.w;
    Bs[0][acol+0][arow]=w0.x; Bs[0][acol+1][arow]=w0.y; Bs[0][acol+2][arow]=w0.z; Bs[0][acol+3][arow]=w0.w;
    Bs[0][acol+4][arow]=w1.x; Bs[0][acol+5][arow]=w1.y; Bs[0][acol+6][arow]=w1.z; Bs[0][acol+7][arow]=w1.w;
    __syncthreads();

    float acc[8][8] = {};
    const int ntile = K/BK;
    for (int t = 0; t < ntile; t++){
        int cur = t & 1;
        if (t+1 < ntile){
            a0 = *(const float4*)(aptr + (t+1)*BK);
            a1 = *(const float4*)(aptr + (t+1)*BK + 4);
            w0 = *(const float4*)(wptr + (t+1)*BK);
            w1 = *(const float4*)(wptr + (t+1)*BK + 4);
        }
        #pragma unroll
        for (int k=0;k<BK;k++){
            float ar[8], br[8];
            #pragma unroll
            for (int m=0;m<8;m++) ar[m] = As[cur][k][ty*8+m];
            #pragma unroll
            for (int n=0;n<8;n++) br[n] = Bs[cur][k][tx*8+n];
            #pragma unroll
            for (int m=0;m<8;m++)
                #pragma unroll
                for (int n=0;n<8;n++)
                    acc[m][n] = fmaf(ar[m], br[n], acc[m][n]);
        }
        if (t+1 < ntile){
            int nxt = cur ^ 1;
            As[nxt][acol+0][arow]=a0.x; As[nxt][acol+1][arow]=a0.y; As[nxt][acol+2][arow]=a0.z; As[nxt][acol+3][arow]=a0.w;
            As[nxt][acol+4][arow]=a1.x; As[nxt][acol+5][arow]=a1.y; As[nxt][acol+6][arow]=a1.z; As[nxt][acol+7][arow]=a1.w;
            Bs[nxt][acol+0][arow]=w0.x; Bs[nxt][acol+1][arow]=w0.y; Bs[nxt][acol+2][arow]=w0.z; Bs[nxt][acol+3][arow]=w0.w;
            Bs[nxt][acol+4][arow]=w1.x; Bs[nxt][acol+5][arow]=w1.y; Bs[nxt][acol+6][arow]=w1.z; Bs[nxt][acol+7][arow]=w1.w;
            __syncthreads();
        }
    }
    #pragma unroll
    for (int m=0;m<8;m++){
        size_t gi = (size_t)(m0 + ty*8 + m);
        #pragma unroll
        for (int n=0;n<8;n++){
            int col = n0 + tx*8 + n;
            float v = acc[m][n] + bias[col];
            if (act == 1) v = leakyf(v);
            else if (act == 2) v = tanhf(v) * 40.0f;
            Cc[gi*(size_t)ldc + col] = v;
        }
    }
}

// channel attention + weighted mean over 4 channels
__global__ void k_attn(int off, const float* __restrict__ avec){
    int i = blockIdx.x, d = threadIdx.x;
    size_t b = (size_t)i*HD + d;
    float x  = d_hid[(size_t)i*768 + off + d];
    float c0 = d_g[b];
    float u1 = d_u1[b], u2 = d_u2[b], u4 = d_u4[b];
    float c1 = fabsf(x - u1), c2 = fabsf(u1 - u2), c3 = fabsf(u2 - u4);
    float ah = avec[256 + d];
    float e0 = fmaxf(c0, 0.f)*ah, e1 = c1*ah, e2 = c2*ah, e3 = c3*ah;
    #pragma unroll
    for (int o=16;o;o>>=1){
        e0 += __shfl_xor_sync(0xffffffffu, e0, o);
        e1 += __shfl_xor_sync(0xffffffffu, e1, o);
        e2 += __shfl_xor_sync(0xffffffffu, e2, o);
        e3 += __shfl_xor_sync(0xffffffffu, e3, o);
    }
    __shared__ float sred[4][8];
    __shared__ float tot[4];
    int w = d >> 5;
    if ((d & 31) == 0){ sred[0][w]=e0; sred[1][w]=e1; sred[2][w]=e2; sred[3][w]=e3; }
    __syncthreads();
    if (d < 4){
        float t = 0.f;
        #pragma unroll
        for (int ww=0; ww<8; ww++) t += sred[d][ww];
        tot[d] = t;
    }
    __syncthreads();
    float E0=tot[0], E1=tot[1], E2=tot[2], E3=tot[3];
    float m = fmaxf(fmaxf(E0,E1), fmaxf(E2,E3));
    float w0=__expf(E0-m), w1=__expf(E1-m), w2=__expf(E2-m), w3=__expf(E3-m);
    float inv = 0.25f / (w0+w1+w2+w3);
    d_hp[b] = inv * (w0*c0 + w1*c1 + w2*c2 + w3*c3);
}

// Threefry-2x32-20, key (0,42)
__device__ __forceinline__ void threefry(unsigned x0, unsigned x1, unsigned& o0, unsigned& o1){
    const unsigned ks0 = 0u, ks1 = 42u, ks2 = 0x1BD11BDAu ^ 42u;
    x0 += ks0; x1 += ks1;
#define TFR(r) { x0 += x1; x1 = (x1<<(r))|(x1>>(32-(r))); x1 ^= x0; }
    TFR(13) TFR(15) TFR(26) TFR(6)   x0+=ks1; x1+=ks2+1u;
    TFR(17) TFR(29) TFR(16) TFR(24)  x0+=ks2; x1+=ks0+2u;
    TFR(13) TFR(15) TFR(26) TFR(6)   x0+=ks0; x1+=ks1+3u;
    TFR(17) TFR(29) TFR(16) TFR(24)  x0+=ks1; x1+=ks2+4u;
    TFR(13) TFR(15) TFR(26) TFR(6)   x0+=ks2; x1+=ks0+5u;
#undef TFR
    o0 = x0; o1 = x1;
}

__device__ __forceinline__ float gumb(unsigned bits){
    float u = __uint_as_float((bits >> 9) | 0x3F800000u) - 1.0f;
    return -logf(-logf(u + 1e-20f) + 1e-20f) * 0.05f;
}

// JAX partitionable threefry: counter = uint64 t -> (hi=0, lo=t), out = o0^o1
__global__ void k_z0(float* __restrict__ z0){
    unsigned t = blockIdx.x*256u + threadIdx.x;
    unsigned o0, o1;
    threefry(0u, t, o0, o1);
    z0[t] = (d_logits[t] + gumb(o0 ^ o1)) * 10.0f;
}

__global__ void k_zeroC(){ d_Cv[blockIdx.x*256 + threadIdx.x] = 0.f; }

// R[row] = lse_j(Z[row,:] - C[b,:]); one warp per row
__global__ void k_row_lse(const float* __restrict__ Z){
    int row  = blockIdx.x*8 + (threadIdx.x>>5);
    int lane = threadIdx.x & 31;
    int b    = row >> 10;
    const float* z = Z + (size_t)row*NNODE;
    const float* c = d_Cv + b*NNODE;
    float v[32];
    float m = -3.4e38f;
    #pragma unroll
    for (int k=0;k<32;k++){ v[k] = z[lane + 32*k] - c[lane + 32*k]; m = fmaxf(m, v[k]); }
    #pragma unroll
    for (int o=16;o;o>>=1) m = fmaxf(m, __shfl_xor_sync(0xffffffffu, m, o));
    float s = 0.f;
    #pragma unroll
    for (int k=0;k<32;k++) s += __expf(v[k] - m);
    #pragma unroll
    for (int o=16;o;o>>=1) s += __shfl_xor_sync(0xffffffffu, s, o);
    if (lane==0) d_Rv[row] = m + __logf(s);
}

// C[b,j] = lse_i(Z[b,i,j] - R[b,i])
__global__ void k_col_lse(const float* __restrict__ Z){
    int b     = blockIdx.x >> 4;
    int chunk = blockIdx.x & 15;
    int jc    = threadIdx.x & 63;
    int q     = threadIdx.x >> 6;
    __shared__ float rs[NNODE];
    for (int k=threadIdx.x; k<NNODE; k+=256) rs[k] = d_Rv[b*NNODE + k];
    __syncthreads();
    const float* z = Z + (size_t)b*NNODE*NNODE + chunk*64 + jc;
    int i0 = q*256;
    float m0=-3.4e38f, m1=-3.4e38f, m2=-3.4e38f, m3=-3.4e38f;
    for (int i=i0; i<i0+256; i+=4){
        m0 = fmaxf(m0, z[(size_t)(i+0)*NNODE] - rs[i+0]);
        m1 = fmaxf(m1, z[(size_t)(i+1)*NNODE] - rs[i+1]);
        m2 = fmaxf(m2, z[(size_t)(i+2)*NNODE] - rs[i+2]);
        m3 = fmaxf(m3, z[(size_t)(i+3)*NNODE] - rs[i+3]);
    }
    float m = fmaxf(fmaxf(m0,m1), fmaxf(m2,m3));
    float s0=0.f,s1=0.f,s2=0.f,s3=0.f;
    for (int i=i0; i<i0+256; i+=4){
        s0 += __expf(z[(size_t)(i+0)*NNODE] - rs[i+0] - m);
        s1 += __expf(z[(size_t)(i+1)*NNODE] - rs[i+1] - m);
        s2 += __expf(z[(size_t)(i+2)*NNODE] - rs[i+2] - m);
        s3 += __expf(z[(size_t)(i+3)*NNODE] - rs[i+3] - m);
    }
    __shared__ float sm[4][64], ss[4][64];
    sm[q][jc] = m; ss[q][jc] = s0+s1+s2+s3;
    __syncthreads();
    if (threadIdx.x < 64){
        int j = threadIdx.x;
        float M = fmaxf(fmaxf(sm[0][j],sm[1][j]), fmaxf(sm[2][j],sm[3][j]));
        float S = ss[0][j]*__expf(sm[0][j]-M) + ss[1][j]*__expf(sm[1][j]-M)
                + ss[2][j]*__expf(sm[2][j]-M) + ss[3][j]*__expf(sm[3][j]-M);
        d_Cv[b*NNODE + chunk*64 + j] = M + __logf(S);
    }
}

// T[b,j] = sum_i exp(Z - R - C)
__global__ void k_col_T(const float* __restrict__ Z){
    int b     = blockIdx.x >> 4;
    int chunk = blockIdx.x & 15;
    int jc    = threadIdx.x & 63;
    int q     = threadIdx.x >> 6;
    __shared__ float rs[NNODE];
    for (int k=threadIdx.x; k<NNODE; k+=256) rs[k] = d_Rv[b*NNODE + k];
    __syncthreads();
    float cj = d_Cv[b*NNODE + chunk*64 + jc];
    const float* z = Z + (size_t)b*NNODE*NNODE + chunk*64 + jc;
    int i0 = q*256;
    float s0=0.f,s1=0.f,s2=0.f,s3=0.f;
    for (int i=i0; i<i0+256; i+=4){
        s0 += __expf(z[(size_t)(i+0)*NNODE] - rs[i+0] - cj);
        s1 += __expf(z[(size_t)(i+1)*NNODE] - rs[i+1] - cj);
        s2 += __expf(z[(size_t)(i+2)*NNODE] - rs[i+2] - cj);
        s3 += __expf(z[(size_t)(i+3)*NNODE] - rs[i+3] - cj);
    }
    __shared__ float ss[4][64];
    ss[q][jc] = s0+s1+s2+s3;
    __syncthreads();
    if (threadIdx.x < 64){
        int j = threadIdx.x;
        d_Tv[b*NNODE + chunk*64 + j] = ss[0][j]+ss[1][j]+ss[2][j]+ss[3][j];
    }
}

__global__ void k_final(const float* __restrict__ Z, float* __restrict__ P){
    size_t t = (size_t)blockIdx.x*256 + threadIdx.x;
    int row = (int)(t >> 10);
    int b   = row >> 10;
    int j   = (int)(t & 1023);
    P[t] = __expf(Z[t] - d_Rv[row] - d_Cv[b*NNODE + j]) / d_Tv[b*NNODE + j];
}

extern "C" void kernel_launch(void* const* d_in, const int* in_sizes, int n_in,
                              void* d_out, int out_size) {
    const float* X      = (const float*)d_in[0];
    const float* adj    = (const float*)d_in[1];
    const float* w_in   = (const float*)d_in[2];
    const float* b_in   = (const float*)d_in[3];
    const float* cw1    = (const float*)d_in[4];
    const float* cb1    = (const float*)d_in[5];
    const float* cw2    = (const float*)d_in[6];
    const float* cb2    = (const float*)d_in[7];
    const float* ca     = (const float*)d_in[8];
    const float* m1w    = (const float*)d_in[9];
    const float* m1b    = (const float*)d_in[10];
    const float* m2w    = (const float*)d_in[11];
    const float* m2b    = (const float*)d_in[12];
    float* Pout = (float*)d_out;
    float* Z0   = Pout + (size_t)TOTEL;

    float *hid, *hs, *g, *u1, *u2, *u3, *u4, *hp, *mid, *lg;
    cudaGetSymbolAddress((void**)&hid, d_hid);
    cudaGetSymbolAddress((void**)&hs,  d_hs);
    cudaGetSymbolAddress((void**)&g,   d_g);
    cudaGetSymbolAddress((void**)&u1,  d_u1);
    cudaGetSymbolAddress((void**)&u2,  d_u2);
    cudaGetSymbolAddress((void**)&u3,  d_u3);
    cudaGetSymbolAddress((void**)&u4,  d_u4);
    cudaGetSymbolAddress((void**)&hp,  d_hp);
    cudaGetSymbolAddress((void**)&mid, d_mid);
    cudaGetSymbolAddress((void**)&lg,  d_logits);
    float *dis, *invdeg;
    cudaGetSymbolAddress((void**)&dis,    d_dis);
    cudaGetSymbolAddress((void**)&invdeg, d_invdeg);

    k_adj_stats<<<NROWS/8, 256>>>(adj);

    // h0 = X @ w_in^T + b_in
    k_gemm_nt<<<dim3(2,128), 256>>>(X, 128, w_in, 128, b_in, hid, 768, 0);

    dim3 bg(2, 8, 16);
    for (int l = 0; l < 2; l++){
        int off  = 256*l;
        int offn = 256*(l+1);
        k_scale_hs<<<NROWS*HD/256, 256>>>(off);
        k_bgemm<<<bg, 256>>>(adj, hs, 256, g,  256, 1, hs, 256, dis);
        k_bgemm<<<bg, 256>>>(adj, hid+off, 768, u1, 256, 2, hid+off, 768, invdeg);
        k_bgemm<<<bg, 256>>>(adj, u1, 256, u2, 256, 2, u1, 256, invdeg);
        k_bgemm<<<bg, 256>>>(adj, u2, 256, u3, 256, 2, u2, 256, invdeg);
        k_bgemm<<<bg, 256>>>(adj, u3, 256, u4, 256, 2, u3, 256, invdeg);
        k_attn<<<NROWS, 256>>>(off, ca + l*512);
        k_gemm_nt<<<dim3(2,128), 256>>>(hp,  256, cw1 + l*65536, 256, cb1 + l*256, mid, 256, 1);
        k_gemm_nt<<<dim3(2,128), 256>>>(mid, 256, cw2 + l*65536, 256, cb2 + l*256, hid + offn, 768, 1);
    }

    // mlp1 + mlp2
    k_gemm_nt<<<dim3(2,128), 256>>>(hid, 768, m1w, 768, m1b, mid, 256, 1);
    k_gemm_nt<<<dim3(8,128), 256>>>(mid, 256, m2w, 256, m2b, lg, 1024, 2);

    // Z0 = (logits + gumbel)/tau  (gsinit output)
    k_z0<<<TOTEL/256, 256>>>(Z0);

    // Sinkhorn: rank-1 log-domain state (R, C)
    k_zeroC<<<NROWS/256, 256>>>();
    for (int it = 0; it < 20; it++){
        k_row_lse<<<NROWS/8, 256>>>(Z0);
        k_col_lse<<<256, 256>>>(Z0);
    }
    k_row_lse<<<NROWS/8, 256>>>(Z0);
    k_col_T  <<<256, 256>>>(Z0);
    k_final  <<<TOTEL/256, 256>>>(Z0, Pout);
}